// round 13
// baseline (speedup 1.0000x reference)
#include <cuda_runtime.h>
#include <cuda_bf16.h>
#include <cstdint>

// Problem dims
#define BATCH 32
#define TLEN  2048
#define IDIM  512
#define HEADS 16
#define DDIM  64
#define MROWS (BATCH * TLEN)      // 65536
#define NCOLS (HEADS * DDIM)      // 1024
#define KTOT  1536                // split-GEMM reduction (3 segments)
#define KX    1024                // g_xs cols [hi|lo]; segment 2 re-reads hi

// GEMM tiling (proven R8 config): 128x128 CTA, 4 warps 64x64, BK=32, 5 stages
#define BM 128
#define BK 32
#define NT (KTOT / BK)            // 48
#define STAGES 5
#define ROWB 80                   // 32*2 + 16 pad (conflict-free ldmatrix)
#define STAGE_B (2 * 128 * ROWB)  // 20480
#define SMEM_GEMM (STAGES * STAGE_B)  // 102400

// Scan chunking (single-pass decoupled lookback, register-resident chunks)
#define NCH 128
#define CL  (TLEN / NCH)          // 16
#define AGG_STRIDE 192

// Scratch (device globals; allocation-free)
__device__ __nv_bfloat16 g_xs[(size_t)MROWS * KX];              // 128 MB split-X
__device__ __nv_bfloat16 g_wv[(size_t)NCOLS * KTOT];            // 3 MB  W_v
__device__ __nv_bfloat16 g_wkq[(size_t)2 * NCOLS * KTOT];       // 6 MB  W_kq
__device__ float g_v[(size_t)MROWS * NCOLS];                    // 256 MB v proj
__device__ float g_s[(size_t)BATCH * HEADS * TLEN];             // 4 MB scores
__device__ float g_agg[(size_t)BATCH * HEADS * NCH * AGG_STRIDE]; // 50 MB
__device__ int   g_flag[BATCH * HEADS * NCH];                   // 256 KB flags

// ---------------------------------------------------------------------------
// PTX helpers (family-portable)
// ---------------------------------------------------------------------------
__device__ __forceinline__ uint32_t smem_u32(const void* p) {
    uint32_t a;
    asm("{ .reg .u64 t; cvta.to.shared.u64 t, %1; cvt.u32.u64 %0, t; }" : "=r"(a) : "l"(p));
    return a;
}
__device__ __forceinline__ void cp_async16(uint32_t dst, const void* src) {
    asm volatile("cp.async.cg.shared.global [%0], [%1], 16;" :: "r"(dst), "l"(src));
}
__device__ __forceinline__ void cp_commit() { asm volatile("cp.async.commit_group;" ::: "memory"); }
__device__ __forceinline__ void cp_wait3()  { asm volatile("cp.async.wait_group 3;" ::: "memory"); }
__device__ __forceinline__ void cp_wait0()  { asm volatile("cp.async.wait_group 0;" ::: "memory"); }

__device__ __forceinline__ void ldsm_x4(uint32_t* r, uint32_t addr) {
    asm volatile("ldmatrix.sync.aligned.m8n8.x4.shared.b16 {%0,%1,%2,%3}, [%4];"
                 : "=r"(r[0]), "=r"(r[1]), "=r"(r[2]), "=r"(r[3]) : "r"(addr));
}
__device__ __forceinline__ void mma16816(float* c, const uint32_t* a, uint32_t b0, uint32_t b1) {
    asm volatile("mma.sync.aligned.m16n8k16.row.col.f32.bf16.bf16.f32 "
                 "{%0,%1,%2,%3}, {%4,%5,%6,%7}, {%8,%9}, {%0,%1,%2,%3};"
                 : "+f"(c[0]), "+f"(c[1]), "+f"(c[2]), "+f"(c[3])
                 : "r"(a[0]), "r"(a[1]), "r"(a[2]), "r"(a[3]), "r"(b0), "r"(b1));
}

__device__ __forceinline__ void stcs_f2(float* p, float2 v) {
    asm volatile("st.global.cs.v2.f32 [%0], {%1, %2};" :: "l"(p), "f"(v.x), "f"(v.y) : "memory");
}
__device__ __forceinline__ float2 ldcs_f2(const float* p) {
    float2 v;
    asm volatile("ld.global.cs.v2.f32 {%0, %1}, [%2];" : "=f"(v.x), "=f"(v.y) : "l"(p));
    return v;
}

// A-tile source column for reduction chunk kt (hi reuse in segment 2)
__device__ __forceinline__ int a_src_col(int kt) { return (kt < 32 ? kt : kt - 32) * BK; }

__device__ __forceinline__ void osmx_combine(float2& num, float& den, float& mx,
                                             float2 anum, float aden, float amx) {
    float nmx = fmaxf(mx, amx);
    float e1 = __expf(mx - nmx);
    float e2 = __expf(amx - nmx);
    den = den * e1 + aden * e2;
    num.x = num.x * e1 + anum.x * e2;
    num.y = num.y * e1 + anum.y * e2;
    mx = nmx;
}

// ---------------------------------------------------------------------------
// K0a: split X -> bf16 [hi | lo], vectorized (validated R11)
// ---------------------------------------------------------------------------
__global__ void convx_kernel(const float4* __restrict__ x) {
    size_t e = (size_t)blockIdx.x * blockDim.x + threadIdx.x;
    if (e >= (size_t)MROWS * IDIM / 4) return;
    size_t m = e >> 7;
    int k = (int)(e & 127) * 4;
    float4 v = x[e];
    __nv_bfloat16 hx = __float2bfloat16(v.x);
    __nv_bfloat16 hy = __float2bfloat16(v.y);
    __nv_bfloat16 hz = __float2bfloat16(v.z);
    __nv_bfloat16 hw = __float2bfloat16(v.w);
    __nv_bfloat162 hi01 = __nv_bfloat162(hx, hy);
    __nv_bfloat162 hi23 = __nv_bfloat162(hz, hw);
    __nv_bfloat162 lo01 = __nv_bfloat162(__float2bfloat16(v.x - __bfloat162float(hx)),
                                         __float2bfloat16(v.y - __bfloat162float(hy)));
    __nv_bfloat162 lo23 = __nv_bfloat162(__float2bfloat16(v.z - __bfloat162float(hz)),
                                         __float2bfloat16(v.w - __bfloat162float(hw)));
    __nv_bfloat16* row = g_xs + m * KX;
    *(__nv_bfloat162*)(row + k)           = hi01;
    *(__nv_bfloat162*)(row + k + 2)       = hi23;
    *(__nv_bfloat162*)(row + 512 + k)     = lo01;
    *(__nv_bfloat162*)(row + 512 + k + 2) = lo23;
}

// ---------------------------------------------------------------------------
// K0b: split W + zero lookback flags (folded; spare threads clear flags)
// ---------------------------------------------------------------------------
__global__ void convw_kernel(const float* __restrict__ W) {
    size_t e = (size_t)blockIdx.x * blockDim.x + threadIdx.x;
    if (e < BATCH * HEADS * NCH) g_flag[e] = 0;
    if (e >= 3ull * IDIM * NCOLS) return;
    int c = (int)(e / (IDIM * NCOLS));
    int r = (int)(e % (IDIM * NCOLS));
    int k = r >> 10;
    int n = r & 1023;
    int h = n >> 6, d = n & 63;
    float v = W[(size_t)k * (HEADS * DDIM * 3) + h * (DDIM * 3) + d * 3 + c];
    __nv_bfloat16 hi = __float2bfloat16(v);
    __nv_bfloat16 lo = __float2bfloat16(v - __bfloat162float(hi));
    __nv_bfloat16* base;
    if (c == 1)      base = g_wv + (size_t)n * KTOT;
    else if (c == 0) base = g_wkq + ((size_t)h * 128 + d) * KTOT;
    else             base = g_wkq + ((size_t)h * 128 + 64 + d) * KTOT;
    base[k] = hi;
    base[512 + k] = hi;
    base[1024 + k] = lo;
}

// ---------------------------------------------------------------------------
// K1: unified GEMM (R8 config). grid.x: 0..7 v; 8..23 head kq.
// ---------------------------------------------------------------------------
__global__ __launch_bounds__(128, 2) void gemm_kernel() {
    extern __shared__ char smem[];
    const int tid = threadIdx.x;
    const int wid = tid >> 5;
    const int lane = tid & 31;

    const int bx = blockIdx.x;
    const int bm = blockIdx.y * BM;
    const int wm = wid & 1;
    const int wn = wid >> 1;
    const bool is_v = (bx < 8);

    const uint32_t sb = smem_u32(smem);

    const __nv_bfloat16* __restrict__ Ag = g_xs + (size_t)bm * KX;
    const __nv_bfloat16* __restrict__ Bg = is_v
        ? g_wv + (size_t)bx * 128 * KTOT
        : g_wkq + (size_t)(bx - 8) * 128 * KTOT;

    auto load_tile = [&](int kt, int s) {
        uint32_t aS = sb + s * STAGE_B;
        uint32_t bS = aS + 128 * ROWB;
        const __nv_bfloat16* ag = Ag + a_src_col(kt);
        const __nv_bfloat16* bg = Bg + kt * BK;
#pragma unroll
        for (int i = 0; i < 4; i++) {
            int idx = tid + i * 128;
            int row = idx >> 2, cc = idx & 3;
            cp_async16(aS + row * ROWB + cc * 16, ag + (size_t)row * KX + cc * 8);
        }
#pragma unroll
        for (int i = 0; i < 4; i++) {
            int idx = tid + i * 128;
            int row = idx >> 2, cc = idx & 3;
            cp_async16(bS + row * ROWB + cc * 16, bg + (size_t)row * KTOT + cc * 8);
        }
        cp_commit();
    };

    load_tile(0, 0);
    load_tile(1, 1);
    load_tile(2, 2);
    load_tile(3, 3);

    float acc[4][8][4];
#pragma unroll
    for (int mi = 0; mi < 4; mi++)
#pragma unroll
        for (int j = 0; j < 8; j++)
#pragma unroll
            for (int q = 0; q < 4; q++) acc[mi][j][q] = 0.0f;

    const int a_row  = wm * 64 + (lane & 15);
    const int a_byte = (lane >> 4) * 16;
    const int b_row  = wn * 64 + ((lane & 16) >> 1) + (lane & 7);
    const int b_byte = ((lane >> 3) & 1) * 16;

    for (int kt = 0; kt < NT; ++kt) {
        cp_wait3();
        __syncthreads();

        int nx = kt + STAGES - 1;
        if (nx < NT) load_tile(nx, nx % STAGES);
        else cp_commit();

        const int s = kt % STAGES;
        const uint32_t aS = sb + s * STAGE_B;
        const uint32_t bS = aS + 128 * ROWB;

#pragma unroll
        for (int ks = 0; ks < 2; ++ks) {
            uint32_t a[4][4], b[4][4];
#pragma unroll
            for (int mi = 0; mi < 4; mi++)
                ldsm_x4(a[mi], aS + (a_row + 16 * mi) * ROWB + ks * 32 + a_byte);
#pragma unroll
            for (int jp = 0; jp < 4; jp++)
                ldsm_x4(b[jp], bS + (b_row + 16 * jp) * ROWB + ks * 32 + b_byte);
#pragma unroll
            for (int mi = 0; mi < 4; mi++)
#pragma unroll
                for (int j = 0; j < 8; j++)
                    mma16816(acc[mi][j], a[mi], b[j >> 1][(j & 1) * 2], b[j >> 1][(j & 1) * 2 + 1]);
        }
    }

    cp_wait0();
    __syncthreads();

    const int tr = lane >> 2;
    const int tc = (lane & 3) * 2;

    if (is_v) {
        const int bn = bx * 128;
#pragma unroll
        for (int mi = 0; mi < 4; mi++) {
            int row0 = bm + wm * 64 + mi * 16 + tr;
#pragma unroll
            for (int j = 0; j < 8; j++) {
                int col = bn + wn * 64 + j * 8 + tc;
                stcs_f2(g_v + (size_t)row0 * NCOLS + col,       make_float2(acc[mi][j][0], acc[mi][j][1]));
                stcs_f2(g_v + (size_t)(row0 + 8) * NCOLS + col, make_float2(acc[mi][j][2], acc[mi][j][3]));
            }
        }
    } else {
        const int h = bx - 8;
        float* sk = (float*)smem;                // 128 x 65 exchange
        if (wn == 0) {
#pragma unroll
            for (int mi = 0; mi < 4; mi++) {
                int row = wm * 64 + mi * 16 + tr;
#pragma unroll
                for (int j = 0; j < 8; j++) {
                    int col = j * 8 + tc;
                    sk[row * 65 + col]           = acc[mi][j][0];
                    sk[row * 65 + col + 1]       = acc[mi][j][1];
                    sk[(row + 8) * 65 + col]     = acc[mi][j][2];
                    sk[(row + 8) * 65 + col + 1] = acc[mi][j][3];
                }
            }
        }
        __syncthreads();
        if (wn == 1) {
#pragma unroll
            for (int mi = 0; mi < 4; mi++) {
                int row = wm * 64 + mi * 16 + tr;
                float p0 = 0.0f, p1 = 0.0f;
#pragma unroll
                for (int j = 0; j < 8; j++) {
                    int col = j * 8 + tc;
                    p0 += acc[mi][j][0] * sk[row * 65 + col] + acc[mi][j][1] * sk[row * 65 + col + 1];
                    p1 += acc[mi][j][2] * sk[(row + 8) * 65 + col] + acc[mi][j][3] * sk[(row + 8) * 65 + col + 1];
                }
                p0 += __shfl_xor_sync(0xFFFFFFFF, p0, 1);
                p0 += __shfl_xor_sync(0xFFFFFFFF, p0, 2);
                p1 += __shfl_xor_sync(0xFFFFFFFF, p1, 1);
                p1 += __shfl_xor_sync(0xFFFFFFFF, p1, 2);
                if ((lane & 3) == 0) {
                    int m0 = bm + row;
                    int b0 = m0 >> 11, t0 = m0 & (TLEN - 1);
                    g_s[((size_t)(b0 * HEADS + h)) * TLEN + t0] = p0;
                    int m1 = m0 + 8;
                    int b1 = m1 >> 11, t1 = m1 & (TLEN - 1);
                    g_s[((size_t)(b1 * HEADS + h)) * TLEN + t1] = p1;
                }
            }
        }
    }
}

// ---------------------------------------------------------------------------
// K2: single-pass lookback scan, register-resident chunks (CL=16) — R8 proven.
// ---------------------------------------------------------------------------
__global__ __launch_bounds__(512, 1) void scan_kernel(float* __restrict__ out) {
    const int b = blockIdx.x;
    const int c = blockIdx.y;
    const int wid = threadIdx.x >> 5;   // head
    const int lane = threadIdx.x & 31;
    const int tid = threadIdx.x;
    const int bh = b * HEADS + wid;

    __shared__ float accbuf[CL][DDIM];

    const float* __restrict__ vbase =
        g_v + ((size_t)b * TLEN + c * CL) * NCOLS + wid * DDIM + 2 * lane;
    const float* __restrict__ sbase = g_s + (size_t)bh * TLEN + c * CL;

    float2 vv[CL];
    float ss[CL];
#pragma unroll
    for (int i = 0; i < CL; i++) vv[i] = ldcs_f2(vbase + (size_t)i * NCOLS);
#pragma unroll
    for (int i = 0; i < CL; i++) ss[i] = sbase[i];

    float2 num = make_float2(0.0f, 0.0f);
    float den = 0.0f, mx = 0.0f;
#pragma unroll
    for (int t = 0; t < CL; ++t) {
        float nmx = fmaxf(mx, ss[t]);
        float md = __expf(mx - nmx);
        float sm = __expf(ss[t] - nmx);
        den = fmaf(den, md, sm);
        num.x = fmaf(num.x, md, vv[t].x * sm);
        num.y = fmaf(num.y, md, vv[t].y * sm);
        mx = nmx;
    }

    float* rec = g_agg + ((size_t)bh * NCH + c) * AGG_STRIDE;
    int* flag = g_flag + bh * NCH + c;

    float2 ex_num = make_float2(0.0f, 0.0f);
    float ex_den = 0.0f, ex_mx = 0.0f;

    if (c == 0) {
        rec[96 + 2 * lane] = num.x;
        rec[96 + 2 * lane + 1] = num.y;
        if (lane == 0) { rec[160] = den; rec[161] = mx; }
        __threadfence();
        __syncwarp();
        if (lane == 0) atomicExch(flag, 2);
    } else {
        rec[2 * lane] = num.x;
        rec[2 * lane + 1] = num.y;
        if (lane == 0) { rec[64] = den; rec[65] = mx; }
        __threadfence();
        __syncwarp();
        if (lane == 0) atomicExch(flag, 1);

        int cc = c - 1;
        for (;;) {
            volatile int* f = (volatile int*)(g_flag + bh * NCH + cc);
            int fv = 0;
            if (lane == 0) {
                while ((fv = *f) == 0) __nanosleep(40);
            }
            fv = __shfl_sync(0xFFFFFFFF, fv, 0);
            const float* r2 = g_agg + ((size_t)bh * NCH + cc) * AGG_STRIDE + (fv == 2 ? 96 : 0);
            float2 anum = make_float2(__ldcg(r2 + 2 * lane), __ldcg(r2 + 2 * lane + 1));
            float aden = __ldcg(r2 + 64);
            float amx = __ldcg(r2 + 65);
            osmx_combine(ex_num, ex_den, ex_mx, anum, aden, amx);
            if (fv == 2) break;
            --cc;
        }

        float2 inum = ex_num;
        float iden = ex_den, imx = ex_mx;
        osmx_combine(inum, iden, imx, num, den, mx);
        rec[96 + 2 * lane] = inum.x;
        rec[96 + 2 * lane + 1] = inum.y;
        if (lane == 0) { rec[160] = iden; rec[161] = imx; }
        __threadfence();
        __syncwarp();
        if (lane == 0) atomicExch(flag, 2);
    }

    num = ex_num; den = ex_den; mx = ex_mx;

    ((float2*)accbuf)[tid] = make_float2(0.0f, 0.0f);
    __syncthreads();

#pragma unroll
    for (int t = 0; t < CL; ++t) {
        float nmx = fmaxf(mx, ss[t]);
        float md = __expf(mx - nmx);
        float sm = __expf(ss[t] - nmx);
        den = fmaf(den, md, sm);
        num.x = fmaf(num.x, md, vv[t].x * sm);
        num.y = fmaf(num.y, md, vv[t].y * sm);
        float inv = 1.0f / den;
        atomicAdd(&accbuf[t][2 * lane],     num.x * inv);
        atomicAdd(&accbuf[t][2 * lane + 1], num.y * inv);
        mx = nmx;
    }
    __syncthreads();

    float* __restrict__ outb = out + ((size_t)b * TLEN + c * CL) * DDIM;
    ((float2*)outb)[tid] = ((float2*)accbuf)[tid];
}

// ---------------------------------------------------------------------------
extern "C" void kernel_launch(void* const* d_in, const int* in_sizes, int n_in,
                              void* d_out, int out_size) {
    const float* x = (const float*)d_in[0];
    const float* w = (const float*)d_in[1];
    if (n_in >= 2 && in_sizes[0] == IDIM * HEADS * DDIM * 3) {
        const float* tmp = x; x = w; w = tmp;
    }
    float* out = (float*)d_out;

    {   // split conversions (+ flag clear folded into convw)
        size_t tx = (size_t)MROWS * IDIM / 4;
        convx_kernel<<<(unsigned)((tx + 255) / 256), 256>>>((const float4*)x);
        size_t tw = 3ull * IDIM * NCOLS;
        convw_kernel<<<(unsigned)((tw + 255) / 256), 256>>>(w);
    }
    {   // unified GEMM: v (8 blocks) + kq scores (16 heads)
        cudaFuncSetAttribute(gemm_kernel, cudaFuncAttributeMaxDynamicSharedMemorySize, SMEM_GEMM);
        dim3 grid(24, MROWS / BM);
        gemm_kernel<<<grid, 128, SMEM_GEMM>>>();
    }
    {   // single-pass register-resident lookback scan -> out
        dim3 gs(BATCH, NCH);
        scan_kernel<<<gs, 512>>>(out);
    }
}

// round 14
// speedup vs baseline: 1.5283x; 1.5283x over previous
#include <cuda_runtime.h>
#include <cuda_bf16.h>
#include <cstdint>

// Problem dims
#define BATCH 32
#define TLEN  2048
#define IDIM  512
#define HEADS 16
#define DDIM  64
#define MROWS (BATCH * TLEN)      // 65536
#define NCOLS (HEADS * DDIM)      // 1024
#define KTOT  1536                // split-GEMM reduction (3 segments)
#define KX    1024                // g_xs cols [hi|lo]; segment 2 re-reads hi

// GEMM tiling (proven R8 config): 128x128 CTA, 4 warps 64x64, BK=32, 5 stages
#define BM 128
#define BK 32
#define NT (KTOT / BK)            // 48
#define STAGES 5
#define ROWB 80                   // 32*2 + 16 pad (conflict-free ldmatrix)
#define STAGE_B (2 * 128 * ROWB)  // 20480
#define SMEM_GEMM (STAGES * STAGE_B)  // 102400

// Scan chunking (single-pass decoupled lookback, register-resident chunks)
#define NCH 128
#define CL  (TLEN / NCH)          // 16
#define AGG_STRIDE 192

// Scratch (device globals; allocation-free)
__device__ __nv_bfloat16 g_xs[(size_t)MROWS * KX];              // 128 MB split-X
__device__ __nv_bfloat16 g_wv[(size_t)NCOLS * KTOT];            // 3 MB  W_v
__device__ __nv_bfloat16 g_wkq[(size_t)2 * NCOLS * KTOT];       // 6 MB  W_kq
__device__ float g_v[(size_t)MROWS * NCOLS];                    // 256 MB v proj
__device__ float g_s[(size_t)BATCH * HEADS * TLEN];             // 4 MB scores
__device__ float g_agg[(size_t)BATCH * HEADS * NCH * AGG_STRIDE]; // 50 MB
__device__ int   g_flag[BATCH * HEADS * NCH];                   // 256 KB flags

// ---------------------------------------------------------------------------
// PTX helpers (family-portable)
// ---------------------------------------------------------------------------
__device__ __forceinline__ uint32_t smem_u32(const void* p) {
    uint32_t a;
    asm("{ .reg .u64 t; cvta.to.shared.u64 t, %1; cvt.u32.u64 %0, t; }" : "=r"(a) : "l"(p));
    return a;
}
__device__ __forceinline__ void cp_async16(uint32_t dst, const void* src) {
    asm volatile("cp.async.cg.shared.global [%0], [%1], 16;" :: "r"(dst), "l"(src));
}
__device__ __forceinline__ void cp_commit() { asm volatile("cp.async.commit_group;" ::: "memory"); }
__device__ __forceinline__ void cp_wait3()  { asm volatile("cp.async.wait_group 3;" ::: "memory"); }
__device__ __forceinline__ void cp_wait0()  { asm volatile("cp.async.wait_group 0;" ::: "memory"); }

__device__ __forceinline__ void ldsm_x4(uint32_t* r, uint32_t addr) {
    asm volatile("ldmatrix.sync.aligned.m8n8.x4.shared.b16 {%0,%1,%2,%3}, [%4];"
                 : "=r"(r[0]), "=r"(r[1]), "=r"(r[2]), "=r"(r[3]) : "r"(addr));
}
__device__ __forceinline__ void mma16816(float* c, const uint32_t* a, uint32_t b0, uint32_t b1) {
    asm volatile("mma.sync.aligned.m16n8k16.row.col.f32.bf16.bf16.f32 "
                 "{%0,%1,%2,%3}, {%4,%5,%6,%7}, {%8,%9}, {%0,%1,%2,%3};"
                 : "+f"(c[0]), "+f"(c[1]), "+f"(c[2]), "+f"(c[3])
                 : "r"(a[0]), "r"(a[1]), "r"(a[2]), "r"(a[3]), "r"(b0), "r"(b1));
}

// A-tile source column for reduction chunk kt (hi reuse in segment 2)
__device__ __forceinline__ int a_src_col(int kt) { return (kt < 32 ? kt : kt - 32) * BK; }

__device__ __forceinline__ void osmx_combine(float2& num, float& den, float& mx,
                                             float2 anum, float aden, float amx) {
    float nmx = fmaxf(mx, amx);
    float e1 = __expf(mx - nmx);
    float e2 = __expf(amx - nmx);
    den = den * e1 + aden * e2;
    num.x = num.x * e1 + anum.x * e2;
    num.y = num.y * e1 + anum.y * e2;
    mx = nmx;
}

// ---------------------------------------------------------------------------
// K0a: split X -> bf16 [hi | lo], vectorized
// ---------------------------------------------------------------------------
__global__ void convx_kernel(const float4* __restrict__ x) {
    size_t e = (size_t)blockIdx.x * blockDim.x + threadIdx.x;
    if (e >= (size_t)MROWS * IDIM / 4) return;
    size_t m = e >> 7;
    int k = (int)(e & 127) * 4;
    float4 v = x[e];
    __nv_bfloat16 hx = __float2bfloat16(v.x);
    __nv_bfloat16 hy = __float2bfloat16(v.y);
    __nv_bfloat16 hz = __float2bfloat16(v.z);
    __nv_bfloat16 hw = __float2bfloat16(v.w);
    __nv_bfloat162 hi01 = __nv_bfloat162(hx, hy);
    __nv_bfloat162 hi23 = __nv_bfloat162(hz, hw);
    __nv_bfloat162 lo01 = __nv_bfloat162(__float2bfloat16(v.x - __bfloat162float(hx)),
                                         __float2bfloat16(v.y - __bfloat162float(hy)));
    __nv_bfloat162 lo23 = __nv_bfloat162(__float2bfloat16(v.z - __bfloat162float(hz)),
                                         __float2bfloat16(v.w - __bfloat162float(hw)));
    __nv_bfloat16* row = g_xs + m * KX;
    *(__nv_bfloat162*)(row + k)           = hi01;
    *(__nv_bfloat162*)(row + k + 2)       = hi23;
    *(__nv_bfloat162*)(row + 512 + k)     = lo01;
    *(__nv_bfloat162*)(row + 512 + k + 2) = lo23;
}

// ---------------------------------------------------------------------------
// K0b: split W + zero lookback flags (folded)
// ---------------------------------------------------------------------------
__global__ void convw_kernel(const float* __restrict__ W) {
    size_t e = (size_t)blockIdx.x * blockDim.x + threadIdx.x;
    if (e < BATCH * HEADS * NCH) g_flag[e] = 0;
    if (e >= 3ull * IDIM * NCOLS) return;
    int c = (int)(e / (IDIM * NCOLS));
    int r = (int)(e % (IDIM * NCOLS));
    int k = r >> 10;
    int n = r & 1023;
    int h = n >> 6, d = n & 63;
    float v = W[(size_t)k * (HEADS * DDIM * 3) + h * (DDIM * 3) + d * 3 + c];
    __nv_bfloat16 hi = __float2bfloat16(v);
    __nv_bfloat16 lo = __float2bfloat16(v - __bfloat162float(hi));
    __nv_bfloat16* base;
    if (c == 1)      base = g_wv + (size_t)n * KTOT;
    else if (c == 0) base = g_wkq + ((size_t)h * 128 + d) * KTOT;
    else             base = g_wkq + ((size_t)h * 128 + 64 + d) * KTOT;
    base[k] = hi;
    base[512 + k] = hi;
    base[1024 + k] = lo;
}

// ---------------------------------------------------------------------------
// K1: unified GEMM (R8 config, plain stores). grid.x: 0..7 v; 8..23 head kq.
// ---------------------------------------------------------------------------
__global__ __launch_bounds__(128, 2) void gemm_kernel() {
    extern __shared__ char smem[];
    const int tid = threadIdx.x;
    const int wid = tid >> 5;
    const int lane = tid & 31;

    const int bx = blockIdx.x;
    const int bm = blockIdx.y * BM;
    const int wm = wid & 1;
    const int wn = wid >> 1;
    const bool is_v = (bx < 8);

    const uint32_t sb = smem_u32(smem);

    const __nv_bfloat16* __restrict__ Ag = g_xs + (size_t)bm * KX;
    const __nv_bfloat16* __restrict__ Bg = is_v
        ? g_wv + (size_t)bx * 128 * KTOT
        : g_wkq + (size_t)(bx - 8) * 128 * KTOT;

    auto load_tile = [&](int kt, int s) {
        uint32_t aS = sb + s * STAGE_B;
        uint32_t bS = aS + 128 * ROWB;
        const __nv_bfloat16* ag = Ag + a_src_col(kt);
        const __nv_bfloat16* bg = Bg + kt * BK;
#pragma unroll
        for (int i = 0; i < 4; i++) {
            int idx = tid + i * 128;
            int row = idx >> 2, cc = idx & 3;
            cp_async16(aS + row * ROWB + cc * 16, ag + (size_t)row * KX + cc * 8);
        }
#pragma unroll
        for (int i = 0; i < 4; i++) {
            int idx = tid + i * 128;
            int row = idx >> 2, cc = idx & 3;
            cp_async16(bS + row * ROWB + cc * 16, bg + (size_t)row * KTOT + cc * 8);
        }
        cp_commit();
    };

    load_tile(0, 0);
    load_tile(1, 1);
    load_tile(2, 2);
    load_tile(3, 3);

    float acc[4][8][4];
#pragma unroll
    for (int mi = 0; mi < 4; mi++)
#pragma unroll
        for (int j = 0; j < 8; j++)
#pragma unroll
            for (int q = 0; q < 4; q++) acc[mi][j][q] = 0.0f;

    const int a_row  = wm * 64 + (lane & 15);
    const int a_byte = (lane >> 4) * 16;
    const int b_row  = wn * 64 + ((lane & 16) >> 1) + (lane & 7);
    const int b_byte = ((lane >> 3) & 1) * 16;

    for (int kt = 0; kt < NT; ++kt) {
        cp_wait3();
        __syncthreads();

        int nx = kt + STAGES - 1;
        if (nx < NT) load_tile(nx, nx % STAGES);
        else cp_commit();

        const int s = kt % STAGES;
        const uint32_t aS = sb + s * STAGE_B;
        const uint32_t bS = aS + 128 * ROWB;

#pragma unroll
        for (int ks = 0; ks < 2; ++ks) {
            uint32_t a[4][4], b[4][4];
#pragma unroll
            for (int mi = 0; mi < 4; mi++)
                ldsm_x4(a[mi], aS + (a_row + 16 * mi) * ROWB + ks * 32 + a_byte);
#pragma unroll
            for (int jp = 0; jp < 4; jp++)
                ldsm_x4(b[jp], bS + (b_row + 16 * jp) * ROWB + ks * 32 + b_byte);
#pragma unroll
            for (int mi = 0; mi < 4; mi++)
#pragma unroll
                for (int j = 0; j < 8; j++)
                    mma16816(acc[mi][j], a[mi], b[j >> 1][(j & 1) * 2], b[j >> 1][(j & 1) * 2 + 1]);
        }
    }

    cp_wait0();
    __syncthreads();

    const int tr = lane >> 2;
    const int tc = (lane & 3) * 2;

    if (is_v) {
        const int bn = bx * 128;
#pragma unroll
        for (int mi = 0; mi < 4; mi++) {
            int row0 = bm + wm * 64 + mi * 16 + tr;
#pragma unroll
            for (int j = 0; j < 8; j++) {
                int col = bn + wn * 64 + j * 8 + tc;
                *(float2*)(g_v + (size_t)row0 * NCOLS + col)       = make_float2(acc[mi][j][0], acc[mi][j][1]);
                *(float2*)(g_v + (size_t)(row0 + 8) * NCOLS + col) = make_float2(acc[mi][j][2], acc[mi][j][3]);
            }
        }
    } else {
        const int h = bx - 8;
        float* sk = (float*)smem;                // 128 x 65 exchange
        if (wn == 0) {
#pragma unroll
            for (int mi = 0; mi < 4; mi++) {
                int row = wm * 64 + mi * 16 + tr;
#pragma unroll
                for (int j = 0; j < 8; j++) {
                    int col = j * 8 + tc;
                    sk[row * 65 + col]           = acc[mi][j][0];
                    sk[row * 65 + col + 1]       = acc[mi][j][1];
                    sk[(row + 8) * 65 + col]     = acc[mi][j][2];
                    sk[(row + 8) * 65 + col + 1] = acc[mi][j][3];
                }
            }
        }
        __syncthreads();
        if (wn == 1) {
#pragma unroll
            for (int mi = 0; mi < 4; mi++) {
                int row = wm * 64 + mi * 16 + tr;
                float p0 = 0.0f, p1 = 0.0f;
#pragma unroll
                for (int j = 0; j < 8; j++) {
                    int col = j * 8 + tc;
                    p0 += acc[mi][j][0] * sk[row * 65 + col] + acc[mi][j][1] * sk[row * 65 + col + 1];
                    p1 += acc[mi][j][2] * sk[(row + 8) * 65 + col] + acc[mi][j][3] * sk[(row + 8) * 65 + col + 1];
                }
                p0 += __shfl_xor_sync(0xFFFFFFFF, p0, 1);
                p0 += __shfl_xor_sync(0xFFFFFFFF, p0, 2);
                p1 += __shfl_xor_sync(0xFFFFFFFF, p1, 1);
                p1 += __shfl_xor_sync(0xFFFFFFFF, p1, 2);
                if ((lane & 3) == 0) {
                    int m0 = bm + row;
                    int b0 = m0 >> 11, t0 = m0 & (TLEN - 1);
                    g_s[((size_t)(b0 * HEADS + h)) * TLEN + t0] = p0;
                    int m1 = m0 + 8;
                    int b1 = m1 >> 11, t1 = m1 & (TLEN - 1);
                    g_s[((size_t)(b1 * HEADS + h)) * TLEN + t1] = p1;
                }
            }
        }
    }
}

// ---------------------------------------------------------------------------
// K2: single-pass lookback scan, register-resident chunks (CL=16) — R8 proven,
//     plain loads (L2 reuse from GEMM epilogue is load-bearing).
// ---------------------------------------------------------------------------
__global__ __launch_bounds__(512, 1) void scan_kernel(float* __restrict__ out) {
    const int b = blockIdx.x;
    const int c = blockIdx.y;
    const int wid = threadIdx.x >> 5;   // head
    const int lane = threadIdx.x & 31;
    const int tid = threadIdx.x;
    const int bh = b * HEADS + wid;

    __shared__ float accbuf[CL][DDIM];

    const float* __restrict__ vbase =
        g_v + ((size_t)b * TLEN + c * CL) * NCOLS + wid * DDIM + 2 * lane;
    const float* __restrict__ sbase = g_s + (size_t)bh * TLEN + c * CL;

    float2 vv[CL];
    float ss[CL];
#pragma unroll
    for (int i = 0; i < CL; i++) vv[i] = *(const float2*)(vbase + (size_t)i * NCOLS);
#pragma unroll
    for (int i = 0; i < CL; i++) ss[i] = sbase[i];

    float2 num = make_float2(0.0f, 0.0f);
    float den = 0.0f, mx = 0.0f;
#pragma unroll
    for (int t = 0; t < CL; ++t) {
        float nmx = fmaxf(mx, ss[t]);
        float md = __expf(mx - nmx);
        float sm = __expf(ss[t] - nmx);
        den = fmaf(den, md, sm);
        num.x = fmaf(num.x, md, vv[t].x * sm);
        num.y = fmaf(num.y, md, vv[t].y * sm);
        mx = nmx;
    }

    float* rec = g_agg + ((size_t)bh * NCH + c) * AGG_STRIDE;
    int* flag = g_flag + bh * NCH + c;

    float2 ex_num = make_float2(0.0f, 0.0f);
    float ex_den = 0.0f, ex_mx = 0.0f;

    if (c == 0) {
        rec[96 + 2 * lane] = num.x;
        rec[96 + 2 * lane + 1] = num.y;
        if (lane == 0) { rec[160] = den; rec[161] = mx; }
        __threadfence();
        __syncwarp();
        if (lane == 0) atomicExch(flag, 2);
    } else {
        rec[2 * lane] = num.x;
        rec[2 * lane + 1] = num.y;
        if (lane == 0) { rec[64] = den; rec[65] = mx; }
        __threadfence();
        __syncwarp();
        if (lane == 0) atomicExch(flag, 1);

        int cc = c - 1;
        for (;;) {
            volatile int* f = (volatile int*)(g_flag + bh * NCH + cc);
            int fv = 0;
            if (lane == 0) {
                while ((fv = *f) == 0) __nanosleep(40);
            }
            fv = __shfl_sync(0xFFFFFFFF, fv, 0);
            const float* r2 = g_agg + ((size_t)bh * NCH + cc) * AGG_STRIDE + (fv == 2 ? 96 : 0);
            float2 anum = make_float2(__ldcg(r2 + 2 * lane), __ldcg(r2 + 2 * lane + 1));
            float aden = __ldcg(r2 + 64);
            float amx = __ldcg(r2 + 65);
            osmx_combine(ex_num, ex_den, ex_mx, anum, aden, amx);
            if (fv == 2) break;
            --cc;
        }

        float2 inum = ex_num;
        float iden = ex_den, imx = ex_mx;
        osmx_combine(inum, iden, imx, num, den, mx);
        rec[96 + 2 * lane] = inum.x;
        rec[96 + 2 * lane + 1] = inum.y;
        if (lane == 0) { rec[160] = iden; rec[161] = imx; }
        __threadfence();
        __syncwarp();
        if (lane == 0) atomicExch(flag, 2);
    }

    num = ex_num; den = ex_den; mx = ex_mx;

    ((float2*)accbuf)[tid] = make_float2(0.0f, 0.0f);
    __syncthreads();

#pragma unroll
    for (int t = 0; t < CL; ++t) {
        float nmx = fmaxf(mx, ss[t]);
        float md = __expf(mx - nmx);
        float sm = __expf(ss[t] - nmx);
        den = fmaf(den, md, sm);
        num.x = fmaf(num.x, md, vv[t].x * sm);
        num.y = fmaf(num.y, md, vv[t].y * sm);
        float inv = 1.0f / den;
        atomicAdd(&accbuf[t][2 * lane],     num.x * inv);
        atomicAdd(&accbuf[t][2 * lane + 1], num.y * inv);
        mx = nmx;
    }
    __syncthreads();

    float* __restrict__ outb = out + ((size_t)b * TLEN + c * CL) * DDIM;
    ((float2*)outb)[tid] = ((float2*)accbuf)[tid];
}

// ---------------------------------------------------------------------------
extern "C" void kernel_launch(void* const* d_in, const int* in_sizes, int n_in,
                              void* d_out, int out_size) {
    const float* x = (const float*)d_in[0];
    const float* w = (const float*)d_in[1];
    if (n_in >= 2 && in_sizes[0] == IDIM * HEADS * DDIM * 3) {
        const float* tmp = x; x = w; w = tmp;
    }
    float* out = (float*)d_out;

    {   // split conversions (+ flag clear folded into convw)
        size_t tx = (size_t)MROWS * IDIM / 4;
        convx_kernel<<<(unsigned)((tx + 255) / 256), 256>>>((const float4*)x);
        size_t tw = 3ull * IDIM * NCOLS;
        convw_kernel<<<(unsigned)((tw + 255) / 256), 256>>>(w);
    }
    {   // unified GEMM: v (8 blocks) + kq scores (16 heads)
        cudaFuncSetAttribute(gemm_kernel, cudaFuncAttributeMaxDynamicSharedMemorySize, SMEM_GEMM);
        dim3 grid(24, MROWS / BM);
        gemm_kernel<<<grid, 128, SMEM_GEMM>>>();
    }
    {   // single-pass register-resident lookback scan -> out
        dim3 gs(BATCH, NCH);
        scan_kernel<<<gs, 512>>>(out);
    }
}

// round 15
// speedup vs baseline: 1.6004x; 1.0471x over previous
#include <cuda_runtime.h>
#include <cuda_bf16.h>
#include <cstdint>

// Problem dims
#define BATCH 32
#define TLEN  2048
#define IDIM  512
#define HEADS 16
#define DDIM  64
#define MROWS (BATCH * TLEN)      // 65536
#define NCOLS (HEADS * DDIM)      // 1024
#define KTOT  1536                // split-GEMM reduction (3 segments)
#define KX    1024                // g_xs cols [hi|lo]; segment 2 re-reads hi

// GEMM tiling (proven R8 config): 128x128 CTA, 4 warps 64x64, BK=32, 5 stages
#define BM 128
#define BK 32
#define NT (KTOT / BK)            // 48
#define STAGES 5
#define ROWB 80                   // 32*2 + 16 pad (conflict-free ldmatrix)
#define STAGE_B (2 * 128 * ROWB)  // 20480
#define SMEM_GEMM (STAGES * STAGE_B)  // 102400

// Scan chunking (single-pass decoupled lookback, register-resident chunks)
#define NCH 128
#define CL  (TLEN / NCH)          // 16
#define AGG_STRIDE 192

// Scratch (device globals; allocation-free)
__device__ __nv_bfloat16 g_xs[(size_t)MROWS * KX];              // 128 MB split-X
__device__ __nv_bfloat16 g_wv[(size_t)NCOLS * KTOT];            // 3 MB  W_v
__device__ __nv_bfloat16 g_wkq[(size_t)2 * NCOLS * KTOT];       // 6 MB  W_kq
__device__ float g_v[(size_t)MROWS * NCOLS];                    // 256 MB v proj
__device__ float g_s[(size_t)BATCH * HEADS * TLEN];             // 4 MB scores
__device__ float g_agg[(size_t)BATCH * HEADS * NCH * AGG_STRIDE]; // 50 MB
__device__ int   g_flag[BATCH * HEADS * NCH];                   // 256 KB flags

// ---------------------------------------------------------------------------
// PTX helpers (family-portable)
// ---------------------------------------------------------------------------
__device__ __forceinline__ uint32_t smem_u32(const void* p) {
    uint32_t a;
    asm("{ .reg .u64 t; cvta.to.shared.u64 t, %1; cvt.u32.u64 %0, t; }" : "=r"(a) : "l"(p));
    return a;
}
__device__ __forceinline__ void cp_async16(uint32_t dst, const void* src) {
    asm volatile("cp.async.cg.shared.global [%0], [%1], 16;" :: "r"(dst), "l"(src));
}
__device__ __forceinline__ void cp_commit() { asm volatile("cp.async.commit_group;" ::: "memory"); }
__device__ __forceinline__ void cp_wait3()  { asm volatile("cp.async.wait_group 3;" ::: "memory"); }
__device__ __forceinline__ void cp_wait0()  { asm volatile("cp.async.wait_group 0;" ::: "memory"); }

__device__ __forceinline__ void ldsm_x4(uint32_t* r, uint32_t addr) {
    asm volatile("ldmatrix.sync.aligned.m8n8.x4.shared.b16 {%0,%1,%2,%3}, [%4];"
                 : "=r"(r[0]), "=r"(r[1]), "=r"(r[2]), "=r"(r[3]) : "r"(addr));
}
__device__ __forceinline__ void mma16816(float* c, const uint32_t* a, uint32_t b0, uint32_t b1) {
    asm volatile("mma.sync.aligned.m16n8k16.row.col.f32.bf16.bf16.f32 "
                 "{%0,%1,%2,%3}, {%4,%5,%6,%7}, {%8,%9}, {%0,%1,%2,%3};"
                 : "+f"(c[0]), "+f"(c[1]), "+f"(c[2]), "+f"(c[3])
                 : "r"(a[0]), "r"(a[1]), "r"(a[2]), "r"(a[3]), "r"(b0), "r"(b1));
}

// A-tile source column for reduction chunk kt (hi reuse in segment 2)
__device__ __forceinline__ int a_src_col(int kt) { return (kt < 32 ? kt : kt - 32) * BK; }

__device__ __forceinline__ void osmx_combine(float2& num, float& den, float& mx,
                                             float2 anum, float aden, float amx) {
    float nmx = fmaxf(mx, amx);
    float e1 = __expf(mx - nmx);
    float e2 = __expf(amx - nmx);
    den = den * e1 + aden * e2;
    num.x = num.x * e1 + anum.x * e2;
    num.y = num.y * e1 + anum.y * e2;
    mx = nmx;
}

// ---------------------------------------------------------------------------
// K0a: split X -> bf16 [hi | lo], vectorized
// ---------------------------------------------------------------------------
__global__ void convx_kernel(const float4* __restrict__ x) {
    size_t e = (size_t)blockIdx.x * blockDim.x + threadIdx.x;
    if (e >= (size_t)MROWS * IDIM / 4) return;
    size_t m = e >> 7;
    int k = (int)(e & 127) * 4;
    float4 v = x[e];
    __nv_bfloat16 hx = __float2bfloat16(v.x);
    __nv_bfloat16 hy = __float2bfloat16(v.y);
    __nv_bfloat16 hz = __float2bfloat16(v.z);
    __nv_bfloat16 hw = __float2bfloat16(v.w);
    __nv_bfloat162 hi01 = __nv_bfloat162(hx, hy);
    __nv_bfloat162 hi23 = __nv_bfloat162(hz, hw);
    __nv_bfloat162 lo01 = __nv_bfloat162(__float2bfloat16(v.x - __bfloat162float(hx)),
                                         __float2bfloat16(v.y - __bfloat162float(hy)));
    __nv_bfloat162 lo23 = __nv_bfloat162(__float2bfloat16(v.z - __bfloat162float(hz)),
                                         __float2bfloat16(v.w - __bfloat162float(hw)));
    __nv_bfloat16* row = g_xs + m * KX;
    *(__nv_bfloat162*)(row + k)           = hi01;
    *(__nv_bfloat162*)(row + k + 2)       = hi23;
    *(__nv_bfloat162*)(row + 512 + k)     = lo01;
    *(__nv_bfloat162*)(row + 512 + k + 2) = lo23;
}

// ---------------------------------------------------------------------------
// K0b: split W + zero lookback flags (folded)
// ---------------------------------------------------------------------------
__global__ void convw_kernel(const float* __restrict__ W) {
    size_t e = (size_t)blockIdx.x * blockDim.x + threadIdx.x;
    if (e < BATCH * HEADS * NCH) g_flag[e] = 0;
    if (e >= 3ull * IDIM * NCOLS) return;
    int c = (int)(e / (IDIM * NCOLS));
    int r = (int)(e % (IDIM * NCOLS));
    int k = r >> 10;
    int n = r & 1023;
    int h = n >> 6, d = n & 63;
    float v = W[(size_t)k * (HEADS * DDIM * 3) + h * (DDIM * 3) + d * 3 + c];
    __nv_bfloat16 hi = __float2bfloat16(v);
    __nv_bfloat16 lo = __float2bfloat16(v - __bfloat162float(hi));
    __nv_bfloat16* base;
    if (c == 1)      base = g_wv + (size_t)n * KTOT;
    else if (c == 0) base = g_wkq + ((size_t)h * 128 + d) * KTOT;
    else             base = g_wkq + ((size_t)h * 128 + 64 + d) * KTOT;
    base[k] = hi;
    base[512 + k] = hi;
    base[1024 + k] = lo;
}

// ---------------------------------------------------------------------------
// K1: unified GEMM (R8 config, unchanged). grid.x: 0..7 v; 8..23 head kq.
// ---------------------------------------------------------------------------
__global__ __launch_bounds__(128, 2) void gemm_kernel() {
    extern __shared__ char smem[];
    const int tid = threadIdx.x;
    const int wid = tid >> 5;
    const int lane = tid & 31;

    const int bx = blockIdx.x;
    const int bm = blockIdx.y * BM;
    const int wm = wid & 1;
    const int wn = wid >> 1;
    const bool is_v = (bx < 8);

    const uint32_t sb = smem_u32(smem);

    const __nv_bfloat16* __restrict__ Ag = g_xs + (size_t)bm * KX;
    const __nv_bfloat16* __restrict__ Bg = is_v
        ? g_wv + (size_t)bx * 128 * KTOT
        : g_wkq + (size_t)(bx - 8) * 128 * KTOT;

    auto load_tile = [&](int kt, int s) {
        uint32_t aS = sb + s * STAGE_B;
        uint32_t bS = aS + 128 * ROWB;
        const __nv_bfloat16* ag = Ag + a_src_col(kt);
        const __nv_bfloat16* bg = Bg + kt * BK;
#pragma unroll
        for (int i = 0; i < 4; i++) {
            int idx = tid + i * 128;
            int row = idx >> 2, cc = idx & 3;
            cp_async16(aS + row * ROWB + cc * 16, ag + (size_t)row * KX + cc * 8);
        }
#pragma unroll
        for (int i = 0; i < 4; i++) {
            int idx = tid + i * 128;
            int row = idx >> 2, cc = idx & 3;
            cp_async16(bS + row * ROWB + cc * 16, bg + (size_t)row * KTOT + cc * 8);
        }
        cp_commit();
    };

    load_tile(0, 0);
    load_tile(1, 1);
    load_tile(2, 2);
    load_tile(3, 3);

    float acc[4][8][4];
#pragma unroll
    for (int mi = 0; mi < 4; mi++)
#pragma unroll
        for (int j = 0; j < 8; j++)
#pragma unroll
            for (int q = 0; q < 4; q++) acc[mi][j][q] = 0.0f;

    const int a_row  = wm * 64 + (lane & 15);
    const int a_byte = (lane >> 4) * 16;
    const int b_row  = wn * 64 + ((lane & 16) >> 1) + (lane & 7);
    const int b_byte = ((lane >> 3) & 1) * 16;

    for (int kt = 0; kt < NT; ++kt) {
        cp_wait3();
        __syncthreads();

        int nx = kt + STAGES - 1;
        if (nx < NT) load_tile(nx, nx % STAGES);
        else cp_commit();

        const int s = kt % STAGES;
        const uint32_t aS = sb + s * STAGE_B;
        const uint32_t bS = aS + 128 * ROWB;

#pragma unroll
        for (int ks = 0; ks < 2; ++ks) {
            uint32_t a[4][4], b[4][4];
#pragma unroll
            for (int mi = 0; mi < 4; mi++)
                ldsm_x4(a[mi], aS + (a_row + 16 * mi) * ROWB + ks * 32 + a_byte);
#pragma unroll
            for (int jp = 0; jp < 4; jp++)
                ldsm_x4(b[jp], bS + (b_row + 16 * jp) * ROWB + ks * 32 + b_byte);
#pragma unroll
            for (int mi = 0; mi < 4; mi++)
#pragma unroll
                for (int j = 0; j < 8; j++)
                    mma16816(acc[mi][j], a[mi], b[j >> 1][(j & 1) * 2], b[j >> 1][(j & 1) * 2 + 1]);
        }
    }

    cp_wait0();
    __syncthreads();

    const int tr = lane >> 2;
    const int tc = (lane & 3) * 2;

    if (is_v) {
        const int bn = bx * 128;
#pragma unroll
        for (int mi = 0; mi < 4; mi++) {
            int row0 = bm + wm * 64 + mi * 16 + tr;
#pragma unroll
            for (int j = 0; j < 8; j++) {
                int col = bn + wn * 64 + j * 8 + tc;
                *(float2*)(g_v + (size_t)row0 * NCOLS + col)       = make_float2(acc[mi][j][0], acc[mi][j][1]);
                *(float2*)(g_v + (size_t)(row0 + 8) * NCOLS + col) = make_float2(acc[mi][j][2], acc[mi][j][3]);
            }
        }
    } else {
        const int h = bx - 8;
        float* sk = (float*)smem;                // 128 x 65 exchange
        if (wn == 0) {
#pragma unroll
            for (int mi = 0; mi < 4; mi++) {
                int row = wm * 64 + mi * 16 + tr;
#pragma unroll
                for (int j = 0; j < 8; j++) {
                    int col = j * 8 + tc;
                    sk[row * 65 + col]           = acc[mi][j][0];
                    sk[row * 65 + col + 1]       = acc[mi][j][1];
                    sk[(row + 8) * 65 + col]     = acc[mi][j][2];
                    sk[(row + 8) * 65 + col + 1] = acc[mi][j][3];
                }
            }
        }
        __syncthreads();
        if (wn == 1) {
#pragma unroll
            for (int mi = 0; mi < 4; mi++) {
                int row = wm * 64 + mi * 16 + tr;
                float p0 = 0.0f, p1 = 0.0f;
#pragma unroll
                for (int j = 0; j < 8; j++) {
                    int col = j * 8 + tc;
                    p0 += acc[mi][j][0] * sk[row * 65 + col] + acc[mi][j][1] * sk[row * 65 + col + 1];
                    p1 += acc[mi][j][2] * sk[(row + 8) * 65 + col] + acc[mi][j][3] * sk[(row + 8) * 65 + col + 1];
                }
                p0 += __shfl_xor_sync(0xFFFFFFFF, p0, 1);
                p0 += __shfl_xor_sync(0xFFFFFFFF, p0, 2);
                p1 += __shfl_xor_sync(0xFFFFFFFF, p1, 1);
                p1 += __shfl_xor_sync(0xFFFFFFFF, p1, 2);
                if ((lane & 3) == 0) {
                    int m0 = bm + row;
                    int b0 = m0 >> 11, t0 = m0 & (TLEN - 1);
                    g_s[((size_t)(b0 * HEADS + h)) * TLEN + t0] = p0;
                    int m1 = m0 + 8;
                    int b1 = m1 >> 11, t1 = m1 & (TLEN - 1);
                    g_s[((size_t)(b1 * HEADS + h)) * TLEN + t1] = p1;
                }
            }
        }
    }
}

// ---------------------------------------------------------------------------
// K2: single-pass lookback scan. Scores held 1/lane + shfl-broadcast (reg diet);
//     __launch_bounds__(512, 2) targets 2 CTAs/SM (waves 27 -> 14).
// ---------------------------------------------------------------------------
__global__ __launch_bounds__(512, 2) void scan_kernel(float* __restrict__ out) {
    const int b = blockIdx.x;
    const int c = blockIdx.y;
    const int wid = threadIdx.x >> 5;   // head
    const int lane = threadIdx.x & 31;
    const int tid = threadIdx.x;
    const int bh = b * HEADS + wid;

    __shared__ float accbuf[CL][DDIM];  // 4 KB

    const float* __restrict__ vbase =
        g_v + ((size_t)b * TLEN + c * CL) * NCOLS + wid * DDIM + 2 * lane;
    const float* __restrict__ sbase = g_s + (size_t)bh * TLEN + c * CL;

    // v chunk in registers (MLP=16); scores: lane t holds s[t] (warp-uniform via shfl)
    float2 vv[CL];
#pragma unroll
    for (int i = 0; i < CL; i++) vv[i] = *(const float2*)(vbase + (size_t)i * NCOLS);
    float sval = sbase[lane & (CL - 1)];

    // ---- pass 1: local chunk aggregate ----
    float2 num = make_float2(0.0f, 0.0f);
    float den = 0.0f, mx = 0.0f;
#pragma unroll
    for (int t = 0; t < CL; ++t) {
        float sc = __shfl_sync(0xFFFFFFFF, sval, t);
        float nmx = fmaxf(mx, sc);
        float md = __expf(mx - nmx);
        float sm = __expf(sc - nmx);
        den = fmaf(den, md, sm);
        num.x = fmaf(num.x, md, vv[t].x * sm);
        num.y = fmaf(num.y, md, vv[t].y * sm);
        mx = nmx;
    }

    float* rec = g_agg + ((size_t)bh * NCH + c) * AGG_STRIDE;
    int* flag = g_flag + bh * NCH + c;

    float2 ex_num = make_float2(0.0f, 0.0f);
    float ex_den = 0.0f, ex_mx = 0.0f;

    if (c == 0) {
        rec[96 + 2 * lane] = num.x;
        rec[96 + 2 * lane + 1] = num.y;
        if (lane == 0) { rec[160] = den; rec[161] = mx; }
        __threadfence();
        __syncwarp();
        if (lane == 0) atomicExch(flag, 2);
    } else {
        rec[2 * lane] = num.x;
        rec[2 * lane + 1] = num.y;
        if (lane == 0) { rec[64] = den; rec[65] = mx; }
        __threadfence();
        __syncwarp();
        if (lane == 0) atomicExch(flag, 1);

        int cc = c - 1;
        for (;;) {
            volatile int* f = (volatile int*)(g_flag + bh * NCH + cc);
            int fv = 0;
            if (lane == 0) {
                while ((fv = *f) == 0) __nanosleep(40);
            }
            fv = __shfl_sync(0xFFFFFFFF, fv, 0);
            const float* r2 = g_agg + ((size_t)bh * NCH + cc) * AGG_STRIDE + (fv == 2 ? 96 : 0);
            float2 anum = make_float2(__ldcg(r2 + 2 * lane), __ldcg(r2 + 2 * lane + 1));
            float aden = __ldcg(r2 + 64);
            float amx = __ldcg(r2 + 65);
            osmx_combine(ex_num, ex_den, ex_mx, anum, aden, amx);
            if (fv == 2) break;
            --cc;
        }

        float2 inum = ex_num;
        float iden = ex_den, imx = ex_mx;
        osmx_combine(inum, iden, imx, num, den, mx);
        rec[96 + 2 * lane] = inum.x;
        rec[96 + 2 * lane + 1] = inum.y;
        if (lane == 0) { rec[160] = iden; rec[161] = imx; }
        __threadfence();
        __syncwarp();
        if (lane == 0) atomicExch(flag, 2);
    }

    // ---- pass 2: rescan with carry; head-sum via smem atomics ----
    num = ex_num; den = ex_den; mx = ex_mx;

    ((float2*)accbuf)[tid] = make_float2(0.0f, 0.0f);
    __syncthreads();

#pragma unroll
    for (int t = 0; t < CL; ++t) {
        float sc = __shfl_sync(0xFFFFFFFF, sval, t);
        float nmx = fmaxf(mx, sc);
        float md = __expf(mx - nmx);
        float sm = __expf(sc - nmx);
        den = fmaf(den, md, sm);
        num.x = fmaf(num.x, md, vv[t].x * sm);
        num.y = fmaf(num.y, md, vv[t].y * sm);
        float inv = 1.0f / den;
        atomicAdd(&accbuf[t][2 * lane],     num.x * inv);
        atomicAdd(&accbuf[t][2 * lane + 1], num.y * inv);
        mx = nmx;
    }
    __syncthreads();

    float* __restrict__ outb = out + ((size_t)b * TLEN + c * CL) * DDIM;
    ((float2*)outb)[tid] = ((float2*)accbuf)[tid];
}

// ---------------------------------------------------------------------------
extern "C" void kernel_launch(void* const* d_in, const int* in_sizes, int n_in,
                              void* d_out, int out_size) {
    const float* x = (const float*)d_in[0];
    const float* w = (const float*)d_in[1];
    if (n_in >= 2 && in_sizes[0] == IDIM * HEADS * DDIM * 3) {
        const float* tmp = x; x = w; w = tmp;
    }
    float* out = (float*)d_out;

    {   // split conversions (+ flag clear folded into convw)
        size_t tx = (size_t)MROWS * IDIM / 4;
        convx_kernel<<<(unsigned)((tx + 255) / 256), 256>>>((const float4*)x);
        size_t tw = 3ull * IDIM * NCOLS;
        convw_kernel<<<(unsigned)((tw + 255) / 256), 256>>>(w);
    }
    {   // unified GEMM: v (8 blocks) + kq scores (16 heads)
        cudaFuncSetAttribute(gemm_kernel, cudaFuncAttributeMaxDynamicSharedMemorySize, SMEM_GEMM);
        dim3 grid(24, MROWS / BM);
        gemm_kernel<<<grid, 128, SMEM_GEMM>>>();
    }
    {   // single-pass register-resident lookback scan -> out
        dim3 gs(BATCH, NCH);
        scan_kernel<<<gs, 512>>>(out);
    }
}

// round 16
// speedup vs baseline: 1.6165x; 1.0101x over previous
#include <cuda_runtime.h>
#include <cuda_bf16.h>
#include <cstdint>

// Problem dims
#define BATCH 32
#define TLEN  2048
#define IDIM  512
#define HEADS 16
#define DDIM  64
#define MROWS (BATCH * TLEN)      // 65536
#define NCOLS (HEADS * DDIM)      // 1024
#define KTOT  1536                // split-GEMM reduction (3 segments)
#define KX    1024                // g_xs cols [hi|lo]; segment 2 re-reads hi

// GEMM tiling (proven R8 config): 128x128 CTA, 4 warps 64x64, BK=32, 5 stages
#define BM 128
#define BK 32
#define NT (KTOT / BK)            // 48
#define STAGES 5
#define ROWB 80                   // 32*2 + 16 pad (conflict-free ldmatrix)
#define STAGE_B (2 * 128 * ROWB)  // 20480
#define SMEM_GEMM (STAGES * STAGE_B)  // 102400

// Scan chunking (single-pass decoupled lookback, register-resident chunks)
#define NCH 128
#define CL  (TLEN / NCH)          // 16
#define AGG_STRIDE 192

// Scratch (device globals; allocation-free)
__device__ __nv_bfloat16 g_xs[(size_t)MROWS * KX];              // 128 MB split-X
__device__ __nv_bfloat16 g_wv[(size_t)NCOLS * KTOT];            // 3 MB  W_v
__device__ __nv_bfloat16 g_wkq[(size_t)2 * NCOLS * KTOT];       // 6 MB  W_kq
__device__ float g_v[(size_t)MROWS * NCOLS];                    // 256 MB v proj
__device__ float g_s[(size_t)BATCH * HEADS * TLEN];             // 4 MB  e^s  [bh][t]
__device__ float g_agg[(size_t)BATCH * HEADS * NCH * AGG_STRIDE]; // 50 MB
__device__ int   g_flag[BATCH * HEADS * NCH];                   // 256 KB flags

// ---------------------------------------------------------------------------
// PTX helpers (family-portable)
// ---------------------------------------------------------------------------
__device__ __forceinline__ uint32_t smem_u32(const void* p) {
    uint32_t a;
    asm("{ .reg .u64 t; cvta.to.shared.u64 t, %1; cvt.u32.u64 %0, t; }" : "=r"(a) : "l"(p));
    return a;
}
__device__ __forceinline__ void cp_async16(uint32_t dst, const void* src) {
    asm volatile("cp.async.cg.shared.global [%0], [%1], 16;" :: "r"(dst), "l"(src));
}
__device__ __forceinline__ void cp_commit() { asm volatile("cp.async.commit_group;" ::: "memory"); }
__device__ __forceinline__ void cp_wait3()  { asm volatile("cp.async.wait_group 3;" ::: "memory"); }
__device__ __forceinline__ void cp_wait0()  { asm volatile("cp.async.wait_group 0;" ::: "memory"); }

__device__ __forceinline__ void ldsm_x4(uint32_t* r, uint32_t addr) {
    asm volatile("ldmatrix.sync.aligned.m8n8.x4.shared.b16 {%0,%1,%2,%3}, [%4];"
                 : "=r"(r[0]), "=r"(r[1]), "=r"(r[2]), "=r"(r[3]) : "r"(addr));
}
__device__ __forceinline__ void mma16816(float* c, const uint32_t* a, uint32_t b0, uint32_t b1) {
    asm volatile("mma.sync.aligned.m16n8k16.row.col.f32.bf16.bf16.f32 "
                 "{%0,%1,%2,%3}, {%4,%5,%6,%7}, {%8,%9}, {%0,%1,%2,%3};"
                 : "+f"(c[0]), "+f"(c[1]), "+f"(c[2]), "+f"(c[3])
                 : "r"(a[0]), "r"(a[1]), "r"(a[2]), "r"(a[3]), "r"(b0), "r"(b1));
}

// A-tile source column for reduction chunk kt (hi reuse in segment 2)
__device__ __forceinline__ int a_src_col(int kt) { return (kt < 32 ? kt : kt - 32) * BK; }

// ---------------------------------------------------------------------------
// K0a: split X -> bf16 [hi | lo], vectorized
// ---------------------------------------------------------------------------
__global__ void convx_kernel(const float4* __restrict__ x) {
    size_t e = (size_t)blockIdx.x * blockDim.x + threadIdx.x;
    if (e >= (size_t)MROWS * IDIM / 4) return;
    size_t m = e >> 7;
    int k = (int)(e & 127) * 4;
    float4 v = x[e];
    __nv_bfloat16 hx = __float2bfloat16(v.x);
    __nv_bfloat16 hy = __float2bfloat16(v.y);
    __nv_bfloat16 hz = __float2bfloat16(v.z);
    __nv_bfloat16 hw = __float2bfloat16(v.w);
    __nv_bfloat162 hi01 = __nv_bfloat162(hx, hy);
    __nv_bfloat162 hi23 = __nv_bfloat162(hz, hw);
    __nv_bfloat162 lo01 = __nv_bfloat162(__float2bfloat16(v.x - __bfloat162float(hx)),
                                         __float2bfloat16(v.y - __bfloat162float(hy)));
    __nv_bfloat162 lo23 = __nv_bfloat162(__float2bfloat16(v.z - __bfloat162float(hz)),
                                         __float2bfloat16(v.w - __bfloat162float(hw)));
    __nv_bfloat16* row = g_xs + m * KX;
    *(__nv_bfloat162*)(row + k)           = hi01;
    *(__nv_bfloat162*)(row + k + 2)       = hi23;
    *(__nv_bfloat162*)(row + 512 + k)     = lo01;
    *(__nv_bfloat162*)(row + 512 + k + 2) = lo23;
}

// ---------------------------------------------------------------------------
// K0b: split W + zero lookback flags (folded)
// ---------------------------------------------------------------------------
__global__ void convw_kernel(const float* __restrict__ W) {
    size_t e = (size_t)blockIdx.x * blockDim.x + threadIdx.x;
    if (e < BATCH * HEADS * NCH) g_flag[e] = 0;
    if (e >= 3ull * IDIM * NCOLS) return;
    int c = (int)(e / (IDIM * NCOLS));
    int r = (int)(e % (IDIM * NCOLS));
    int k = r >> 10;
    int n = r & 1023;
    int h = n >> 6, d = n & 63;
    float v = W[(size_t)k * (HEADS * DDIM * 3) + h * (DDIM * 3) + d * 3 + c];
    __nv_bfloat16 hi = __float2bfloat16(v);
    __nv_bfloat16 lo = __float2bfloat16(v - __bfloat162float(hi));
    __nv_bfloat16* base;
    if (c == 1)      base = g_wv + (size_t)n * KTOT;
    else if (c == 0) base = g_wkq + ((size_t)h * 128 + d) * KTOT;
    else             base = g_wkq + ((size_t)h * 128 + 64 + d) * KTOT;
    base[k] = hi;
    base[512 + k] = hi;
    base[1024 + k] = lo;
}

// ---------------------------------------------------------------------------
// K1: unified GEMM (R8 config). grid.x: 0..7 v; 8..23 head kq.
//     kq epilogue now stores e^s (exp moved out of the scan).
// ---------------------------------------------------------------------------
__global__ __launch_bounds__(128, 2) void gemm_kernel() {
    extern __shared__ char smem[];
    const int tid = threadIdx.x;
    const int wid = tid >> 5;
    const int lane = tid & 31;

    const int bx = blockIdx.x;
    const int bm = blockIdx.y * BM;
    const int wm = wid & 1;
    const int wn = wid >> 1;
    const bool is_v = (bx < 8);

    const uint32_t sb = smem_u32(smem);

    const __nv_bfloat16* __restrict__ Ag = g_xs + (size_t)bm * KX;
    const __nv_bfloat16* __restrict__ Bg = is_v
        ? g_wv + (size_t)bx * 128 * KTOT
        : g_wkq + (size_t)(bx - 8) * 128 * KTOT;

    auto load_tile = [&](int kt, int s) {
        uint32_t aS = sb + s * STAGE_B;
        uint32_t bS = aS + 128 * ROWB;
        const __nv_bfloat16* ag = Ag + a_src_col(kt);
        const __nv_bfloat16* bg = Bg + kt * BK;
#pragma unroll
        for (int i = 0; i < 4; i++) {
            int idx = tid + i * 128;
            int row = idx >> 2, cc = idx & 3;
            cp_async16(aS + row * ROWB + cc * 16, ag + (size_t)row * KX + cc * 8);
        }
#pragma unroll
        for (int i = 0; i < 4; i++) {
            int idx = tid + i * 128;
            int row = idx >> 2, cc = idx & 3;
            cp_async16(bS + row * ROWB + cc * 16, bg + (size_t)row * KTOT + cc * 8);
        }
        cp_commit();
    };

    load_tile(0, 0);
    load_tile(1, 1);
    load_tile(2, 2);
    load_tile(3, 3);

    float acc[4][8][4];
#pragma unroll
    for (int mi = 0; mi < 4; mi++)
#pragma unroll
        for (int j = 0; j < 8; j++)
#pragma unroll
            for (int q = 0; q < 4; q++) acc[mi][j][q] = 0.0f;

    const int a_row  = wm * 64 + (lane & 15);
    const int a_byte = (lane >> 4) * 16;
    const int b_row  = wn * 64 + ((lane & 16) >> 1) + (lane & 7);
    const int b_byte = ((lane >> 3) & 1) * 16;

    for (int kt = 0; kt < NT; ++kt) {
        cp_wait3();
        __syncthreads();

        int nx = kt + STAGES - 1;
        if (nx < NT) load_tile(nx, nx % STAGES);
        else cp_commit();

        const int s = kt % STAGES;
        const uint32_t aS = sb + s * STAGE_B;
        const uint32_t bS = aS + 128 * ROWB;

#pragma unroll
        for (int ks = 0; ks < 2; ++ks) {
            uint32_t a[4][4], b[4][4];
#pragma unroll
            for (int mi = 0; mi < 4; mi++)
                ldsm_x4(a[mi], aS + (a_row + 16 * mi) * ROWB + ks * 32 + a_byte);
#pragma unroll
            for (int jp = 0; jp < 4; jp++)
                ldsm_x4(b[jp], bS + (b_row + 16 * jp) * ROWB + ks * 32 + b_byte);
#pragma unroll
            for (int mi = 0; mi < 4; mi++)
#pragma unroll
                for (int j = 0; j < 8; j++)
                    mma16816(acc[mi][j], a[mi], b[j >> 1][(j & 1) * 2], b[j >> 1][(j & 1) * 2 + 1]);
        }
    }

    cp_wait0();
    __syncthreads();

    const int tr = lane >> 2;
    const int tc = (lane & 3) * 2;

    if (is_v) {
        const int bn = bx * 128;
#pragma unroll
        for (int mi = 0; mi < 4; mi++) {
            int row0 = bm + wm * 64 + mi * 16 + tr;
#pragma unroll
            for (int j = 0; j < 8; j++) {
                int col = bn + wn * 64 + j * 8 + tc;
                *(float2*)(g_v + (size_t)row0 * NCOLS + col)       = make_float2(acc[mi][j][0], acc[mi][j][1]);
                *(float2*)(g_v + (size_t)(row0 + 8) * NCOLS + col) = make_float2(acc[mi][j][2], acc[mi][j][3]);
            }
        }
    } else {
        const int h = bx - 8;
        float* sk = (float*)smem;                // 128 x 65 exchange
        if (wn == 0) {
#pragma unroll
            for (int mi = 0; mi < 4; mi++) {
                int row = wm * 64 + mi * 16 + tr;
#pragma unroll
                for (int j = 0; j < 8; j++) {
                    int col = j * 8 + tc;
                    sk[row * 65 + col]           = acc[mi][j][0];
                    sk[row * 65 + col + 1]       = acc[mi][j][1];
                    sk[(row + 8) * 65 + col]     = acc[mi][j][2];
                    sk[(row + 8) * 65 + col + 1] = acc[mi][j][3];
                }
            }
        }
        __syncthreads();
        if (wn == 1) {
#pragma unroll
            for (int mi = 0; mi < 4; mi++) {
                int row = wm * 64 + mi * 16 + tr;
                float p0 = 0.0f, p1 = 0.0f;
#pragma unroll
                for (int j = 0; j < 8; j++) {
                    int col = j * 8 + tc;
                    p0 += acc[mi][j][0] * sk[row * 65 + col] + acc[mi][j][1] * sk[row * 65 + col + 1];
                    p1 += acc[mi][j][2] * sk[(row + 8) * 65 + col] + acc[mi][j][3] * sk[(row + 8) * 65 + col + 1];
                }
                p0 += __shfl_xor_sync(0xFFFFFFFF, p0, 1);
                p0 += __shfl_xor_sync(0xFFFFFFFF, p0, 2);
                p1 += __shfl_xor_sync(0xFFFFFFFF, p1, 1);
                p1 += __shfl_xor_sync(0xFFFFFFFF, p1, 2);
                if ((lane & 3) == 0) {
                    int m0 = bm + row;
                    int b0 = m0 >> 11, t0 = m0 & (TLEN - 1);
                    g_s[((size_t)(b0 * HEADS + h)) * TLEN + t0] = __expf(p0);
                    int m1 = m0 + 8;
                    int b1 = m1 >> 11, t1 = m1 & (TLEN - 1);
                    g_s[((size_t)(b1 * HEADS + h)) * TLEN + t1] = __expf(p1);
                }
            }
        }
    }
}

// ---------------------------------------------------------------------------
// K2: single-pass lookback scan — exp-free prefix sum of (num, den).
//     g_s holds e^s; ratio num/den is normalizer-invariant vs the reference.
// ---------------------------------------------------------------------------
__global__ __launch_bounds__(512, 2) void scan_kernel(float* __restrict__ out) {
    const int b = blockIdx.x;
    const int c = blockIdx.y;
    const int wid = threadIdx.x >> 5;   // head
    const int lane = threadIdx.x & 31;
    const int tid = threadIdx.x;
    const int bh = b * HEADS + wid;

    __shared__ float accbuf[CL][DDIM];  // 4 KB

    const float* __restrict__ vbase =
        g_v + ((size_t)b * TLEN + c * CL) * NCOLS + wid * DDIM + 2 * lane;
    const float* __restrict__ sbase = g_s + (size_t)bh * TLEN + c * CL;

    // v chunk in registers (MLP=16); e^s: lane t holds es[t], shfl-broadcast
    float2 vv[CL];
#pragma unroll
    for (int i = 0; i < CL; i++) vv[i] = *(const float2*)(vbase + (size_t)i * NCOLS);
    float esv = sbase[lane & (CL - 1)];

    // ---- pass 1: local chunk sums ----
    float2 num = make_float2(0.0f, 0.0f);
    float den = 0.0f;
#pragma unroll
    for (int t = 0; t < CL; ++t) {
        float es = __shfl_sync(0xFFFFFFFF, esv, t);
        num.x = fmaf(vv[t].x, es, num.x);
        num.y = fmaf(vv[t].y, es, num.y);
        den += es;
    }

    float* rec = g_agg + ((size_t)bh * NCH + c) * AGG_STRIDE;
    int* flag = g_flag + bh * NCH + c;

    float2 ex_num = make_float2(0.0f, 0.0f);
    float ex_den = 0.0f;

    if (c == 0) {
        rec[96 + 2 * lane] = num.x;
        rec[96 + 2 * lane + 1] = num.y;
        if (lane == 0) rec[160] = den;
        __threadfence();
        __syncwarp();
        if (lane == 0) atomicExch(flag, 2);
    } else {
        rec[2 * lane] = num.x;
        rec[2 * lane + 1] = num.y;
        if (lane == 0) rec[64] = den;
        __threadfence();
        __syncwarp();
        if (lane == 0) atomicExch(flag, 1);

        int cc = c - 1;
        for (;;) {
            volatile int* f = (volatile int*)(g_flag + bh * NCH + cc);
            int fv = 0;
            if (lane == 0) {
                while ((fv = *f) == 0) __nanosleep(40);
            }
            fv = __shfl_sync(0xFFFFFFFF, fv, 0);
            const float* r2 = g_agg + ((size_t)bh * NCH + cc) * AGG_STRIDE + (fv == 2 ? 96 : 0);
            ex_num.x += __ldcg(r2 + 2 * lane);
            ex_num.y += __ldcg(r2 + 2 * lane + 1);
            ex_den   += __ldcg(r2 + 64);
            if (fv == 2) break;
            --cc;
        }

        rec[96 + 2 * lane] = ex_num.x + num.x;
        rec[96 + 2 * lane + 1] = ex_num.y + num.y;
        if (lane == 0) rec[160] = ex_den + den;
        __threadfence();
        __syncwarp();
        if (lane == 0) atomicExch(flag, 2);
    }

    // ---- pass 2: running prefix with carry; head-sum via smem atomics ----
    num = ex_num; den = ex_den;

    ((float2*)accbuf)[tid] = make_float2(0.0f, 0.0f);
    __syncthreads();

#pragma unroll
    for (int t = 0; t < CL; ++t) {
        float es = __shfl_sync(0xFFFFFFFF, esv, t);
        num.x = fmaf(vv[t].x, es, num.x);
        num.y = fmaf(vv[t].y, es, num.y);
        den += es;
        float inv = 1.0f / den;
        atomicAdd(&accbuf[t][2 * lane],     num.x * inv);
        atomicAdd(&accbuf[t][2 * lane + 1], num.y * inv);
    }
    __syncthreads();

    float* __restrict__ outb = out + ((size_t)b * TLEN + c * CL) * DDIM;
    ((float2*)outb)[tid] = ((float2*)accbuf)[tid];
}

// ---------------------------------------------------------------------------
extern "C" void kernel_launch(void* const* d_in, const int* in_sizes, int n_in,
                              void* d_out, int out_size) {
    const float* x = (const float*)d_in[0];
    const float* w = (const float*)d_in[1];
    if (n_in >= 2 && in_sizes[0] == IDIM * HEADS * DDIM * 3) {
        const float* tmp = x; x = w; w = tmp;
    }
    float* out = (float*)d_out;

    {   // split conversions (+ flag clear folded into convw)
        size_t tx = (size_t)MROWS * IDIM / 4;
        convx_kernel<<<(unsigned)((tx + 255) / 256), 256>>>((const float4*)x);
        size_t tw = 3ull * IDIM * NCOLS;
        convw_kernel<<<(unsigned)((tw + 255) / 256), 256>>>(w);
    }
    {   // unified GEMM: v (8 blocks) + kq e^s (16 heads)
        cudaFuncSetAttribute(gemm_kernel, cudaFuncAttributeMaxDynamicSharedMemorySize, SMEM_GEMM);
        dim3 grid(24, MROWS / BM);
        gemm_kernel<<<grid, 128, SMEM_GEMM>>>();
    }
    {   // exp-free prefix-sum lookback scan -> out
        dim3 gs(BATCH, NCH);
        scan_kernel<<<gs, 512>>>(out);
    }
}